// round 1
// baseline (speedup 1.0000x reference)
#include <cuda_runtime.h>
#include <math.h>

// ---------------------------------------------------------------------------
// Scratch (device globals — no allocations allowed)
// ---------------------------------------------------------------------------
__device__ float g_bufA[67108864];   // 256 MB ping
__device__ float g_bufB[67108864];   // 256 MB pong
__device__ float g_latf[32768];      // lat_fine  [8,4,32,32]
__device__ float g_latc[8192];       // lat_coarse[8,4,16,16]
__device__ float g_ent[2048];        // entropy   [8,16,16]
__device__ float g_routed[32768];    // routed    [8,4,32,32]
__device__ float g_thr;

// Output layout (flattened tuple): rec | routed | grain | ent
#define OFF_ROUTED 1572864
#define OFF_GRAIN  1605632
#define OFF_ENT    1607680
#define OUT_FULL   1609728

// ---------------------------------------------------------------------------
// Encoder: two tiny strided 3x3 convs (stride 8 and 16, pad 1), C_in=3, C_out=4
// ---------------------------------------------------------------------------
__global__ void encoder_kernel(const float* __restrict__ x,
                               const float* __restrict__ We0, const float* __restrict__ be0,
                               const float* __restrict__ We1, const float* __restrict__ be1)
{
    int idx = blockIdx.x * blockDim.x + threadIdx.x;
    if (idx < 32768) {
        int n = idx >> 12, c = (idx >> 10) & 3, oy = (idx >> 5) & 31, ox = idx & 31;
        float acc = be0[c];
        for (int ic = 0; ic < 3; ic++)
            for (int ky = 0; ky < 3; ky++) {
                int iy = oy * 8 - 1 + ky;
                if ((unsigned)iy >= 256u) continue;
                for (int kx = 0; kx < 3; kx++) {
                    int ix = ox * 8 - 1 + kx;
                    if ((unsigned)ix >= 256u) continue;
                    acc += x[((n * 3 + ic) * 256 + iy) * 256 + ix] *
                           We0[((c * 3 + ic) * 3 + ky) * 3 + kx];
                }
            }
        g_latf[idx] = acc;
    } else if (idx < 40960) {
        int i2 = idx - 32768;
        int n = i2 >> 10, c = (i2 >> 8) & 3, oy = (i2 >> 4) & 15, ox = i2 & 15;
        float acc = be1[c];
        for (int ic = 0; ic < 3; ic++)
            for (int ky = 0; ky < 3; ky++) {
                int iy = oy * 16 - 1 + ky;
                if ((unsigned)iy >= 256u) continue;
                for (int kx = 0; kx < 3; kx++) {
                    int ix = ox * 16 - 1 + kx;
                    if ((unsigned)ix >= 256u) continue;
                    acc += x[((n * 3 + ic) * 256 + iy) * 256 + ix] *
                           We1[((c * 3 + ic) * 3 + ky) * 3 + kx];
                }
            }
        g_latc[i2] = acc;
    }
}

// ---------------------------------------------------------------------------
// Entropy map: one block per 16x16 patch. Gray -> sort -> windowed KDE -> H.
// Window R: exp(-0.5*(R/0.01)^2) ~ 4e-20, far below the 1e-10 clip floor.
// ---------------------------------------------------------------------------
__global__ void entropy_kernel(const float* __restrict__ x)
{
    __shared__ float g[256];
    __shared__ float red[256];
    int bid = blockIdx.x;                       // b*256 + hp*16 + wp
    int b = bid >> 8, hp = (bid >> 4) & 15, wp = bid & 15;
    int tid = threadIdx.x;
    int py = tid >> 4, px = tid & 15;
    int gy = hp * 16 + py, gx = wp * 16 + px;
    const float* xb = x + (size_t)b * 3 * 65536;
    float gr = 0.299f * xb[gy * 256 + gx]
             + 0.587f * xb[65536 + gy * 256 + gx]
             + 0.114f * xb[131072 + gy * 256 + gx];
    g[tid] = gr;
    __syncthreads();

    // bitonic sort ascending (256 elems, 256 threads)
    for (int k = 2; k <= 256; k <<= 1)
        for (int j = k >> 1; j > 0; j >>= 1) {
            int ixj = tid ^ j;
            if (ixj > tid) {
                float a = g[tid], c2 = g[ixj];
                bool up = (tid & k) == 0;
                if ((a > c2) == up) { g[tid] = c2; g[ixj] = a; }
            }
            __syncthreads();
        }

    // per-bin windowed Gaussian sum
    float vb = tid * (1.0f / 255.0f);
    const float R = 0.0945f;
    float loV = vb - R, hiV = vb + R;
    int lo = 0, hi = 256;
    while (lo < hi) { int m = (lo + hi) >> 1; if (g[m] < loV) lo = m + 1; else hi = m; }
    int s0 = lo;
    lo = s0; hi = 256;
    while (lo < hi) { int m = (lo + hi) >> 1; if (g[m] <= hiV) lo = m + 1; else hi = m; }
    int s1 = lo;
    float S = 0.0f;
    for (int i = s0; i < s1; i++) {
        float d = (g[i] - vb) * 100.0f;
        S += expf(-0.5f * d * d);
    }
    red[tid] = S;
    __syncthreads();
    for (int st = 128; st > 0; st >>= 1) { if (tid < st) red[tid] += red[tid + st]; __syncthreads(); }
    float T = red[0];
    __syncthreads();
    float p = S / T;
    p = fmaxf(p, 1e-10f);
    red[tid] = p * log2f(p);
    __syncthreads();
    for (int st = 128; st > 0; st >>= 1) { if (tid < st) red[tid] += red[tid + st]; __syncthreads(); }
    if (tid == 0) g_ent[bid] = -red[0];
}

// ---------------------------------------------------------------------------
// Median of 2048 entropies (jnp.quantile q=0.5, linear): single-block bitonic.
// ---------------------------------------------------------------------------
__global__ void median_kernel()
{
    __shared__ float s[2048];
    int tid = threadIdx.x;      // 1024 threads
    s[tid] = g_ent[tid];
    s[tid + 1024] = g_ent[tid + 1024];
    __syncthreads();
    for (int k = 2; k <= 2048; k <<= 1)
        for (int j = k >> 1; j > 0; j >>= 1) {
            for (int base = 0; base < 2048; base += 1024) {
                int i = base + tid, ixj = i ^ j;
                if (ixj > i) {
                    float a = s[i], c2 = s[ixj];
                    bool up = (i & k) == 0;
                    if ((a > c2) == up) { s[i] = c2; s[ixj] = a; }
                }
            }
            __syncthreads();
        }
    if (tid == 0) g_thr = 0.5f * (s[1023] + s[1024]);
}

// ---------------------------------------------------------------------------
// Routing + aux outputs
// ---------------------------------------------------------------------------
__global__ void route_kernel(float* __restrict__ out, int write_aux)
{
    int i = blockIdx.x * blockDim.x + threadIdx.x;
    if (i >= 32768) return;
    float thr = g_thr;
    int n = i >> 12, c = (i >> 10) & 3, y = (i >> 5) & 31, xx = i & 31;
    int hp = y >> 1, wp = xx >> 1;
    float e = g_ent[n * 256 + hp * 16 + wp];
    float v = (e > thr) ? g_latf[i]
                        : g_latc[((n * 4 + c) * 16 + hp) * 16 + wp];
    g_routed[i] = v;
    if (write_aux) {
        out[OFF_ROUTED + i] = v;
        if (i < 2048) {
            float ev = g_ent[i];
            out[OFF_GRAIN + i] = (ev > thr) ? 1.0f : 0.0f;
            out[OFF_ENT + i] = ev;
        }
    }
}

// ---------------------------------------------------------------------------
// Generic 3x3 stride-1 pad-1 conv, NCHW. Block: 64 oc x (8x16) px, 256 thr,
// 32 acc/thread (4 oc x 2x4 px). Weights [oc][ic][3][3].
// ---------------------------------------------------------------------------
template<int IC_BLK>
__global__ __launch_bounds__(256) void conv3x3_kernel(
    const float* __restrict__ in, const float* __restrict__ w,
    const float* __restrict__ bias, float* __restrict__ out,
    int C_in, int C_out, int H, int W, int do_relu)
{
    __shared__ float s_in[IC_BLK][10][19];
    __shared__ float s_w[IC_BLK][9][64];
    int tiles_x = W >> 4;
    int ty = blockIdx.x / tiles_x, tx = blockIdx.x - ty * tiles_x;
    int oc0 = blockIdx.y << 6;
    int n = blockIdx.z;
    int y0 = ty << 3, x0 = tx << 4;
    int tid = threadIdx.x;
    int ocg = tid >> 4, pxg = tid & 15;
    int pr = pxg >> 2, pc = pxg & 3;

    float acc[4][2][4];
    #pragma unroll
    for (int o = 0; o < 4; o++)
        #pragma unroll
        for (int dr = 0; dr < 2; dr++)
            #pragma unroll
            for (int dc = 0; dc < 4; dc++) acc[o][dr][dc] = 0.0f;

    const float* in_n = in + (size_t)n * C_in * H * W;
    for (int ic0 = 0; ic0 < C_in; ic0 += IC_BLK) {
        __syncthreads();
        for (int e = tid; e < IC_BLK * 180; e += 256) {
            int ic = e / 180; int rem = e - ic * 180;
            int r = rem / 18;  int cc = rem - r * 18;
            int gy = y0 - 1 + r, gx = x0 - 1 + cc;
            float v = 0.0f;
            if ((unsigned)gy < (unsigned)H && (unsigned)gx < (unsigned)W)
                v = in_n[((size_t)(ic0 + ic) * H + gy) * W + gx];
            s_in[ic][r][cc] = v;
        }
        for (int e = tid; e < IC_BLK * 9 * 64; e += 256) {
            int oc = e / (IC_BLK * 9); int rem = e - oc * (IC_BLK * 9);
            int ic = rem / 9; int k = rem - ic * 9;
            s_w[ic][k][oc] = w[((size_t)(oc0 + oc) * C_in + ic0 + ic) * 9 + k];
        }
        __syncthreads();
        #pragma unroll 1
        for (int ic = 0; ic < IC_BLK; ic++) {
            #pragma unroll
            for (int ky = 0; ky < 3; ky++) {
                #pragma unroll
                for (int kx = 0; kx < 3; kx++) {
                    float wv[4];
                    #pragma unroll
                    for (int o = 0; o < 4; o++) wv[o] = s_w[ic][ky * 3 + kx][(ocg << 2) + o];
                    float iv[2][4];
                    #pragma unroll
                    for (int dr = 0; dr < 2; dr++)
                        #pragma unroll
                        for (int dc = 0; dc < 4; dc++)
                            iv[dr][dc] = s_in[ic][(pr << 1) + dr + ky][(pc << 2) + dc + kx];
                    #pragma unroll
                    for (int o = 0; o < 4; o++)
                        #pragma unroll
                        for (int dr = 0; dr < 2; dr++)
                            #pragma unroll
                            for (int dc = 0; dc < 4; dc++)
                                acc[o][dr][dc] = fmaf(wv[o], iv[dr][dc], acc[o][dr][dc]);
                }
            }
        }
    }
    float* out_n = out + ((size_t)n * C_out + oc0) * H * W;
    #pragma unroll
    for (int o = 0; o < 4; o++) {
        float bv = bias[oc0 + (ocg << 2) + o];
        #pragma unroll
        for (int dr = 0; dr < 2; dr++)
            #pragma unroll
            for (int dc = 0; dc < 4; dc++) {
                float v = acc[o][dr][dc] + bv;
                if (do_relu) v = fmaxf(v, 0.0f);
                out_n[((size_t)((ocg << 2) + o) * H + y0 + (pr << 1) + dr) * W
                      + x0 + (pc << 2) + dc] = v;
            }
    }
}

// ---------------------------------------------------------------------------
// ConvTranspose2d k3 s2 p1 op1, weights [C_in][C_out][3][3], fused bias+relu.
// Block: input tile 4x8 -> output 8x16, 64 oc. Thread: 2 oc x (2x2 quads).
// out(2iy+dy,2ix+dx): y-taps T(0)={(ky=1,+0)}, T(1)={(ky=2,+0),(ky=0,+1)}.
// ---------------------------------------------------------------------------
template<int IC_BLK>
__global__ __launch_bounds__(256) void deconv3x3s2_kernel(
    const float* __restrict__ in, const float* __restrict__ w,
    const float* __restrict__ bias, float* __restrict__ out,
    int C_in, int C_out, int H, int W)   // input dims; output is 2H x 2W
{
    __shared__ float s_in[IC_BLK][5][10];
    __shared__ float s_w[IC_BLK][64][9];
    int tiles_x = W >> 3;
    int ty = blockIdx.x / tiles_x, tx = blockIdx.x - ty * tiles_x;
    int oc0 = blockIdx.y << 6;
    int n = blockIdx.z;
    int y0 = ty << 2, x0 = tx << 3;
    int tid = threadIdx.x;
    int ocg = tid >> 3, qg = tid & 7;
    int qr = qg >> 2, qc = qg & 3;          // quad-group base (qr*2, qc*2)

    float acc[2][2][2][2][2];               // [oc2][qy][qx][dy][dx]
    #pragma unroll
    for (int a = 0; a < 2; a++)
        #pragma unroll
        for (int b = 0; b < 2; b++)
            #pragma unroll
            for (int c = 0; c < 2; c++)
                #pragma unroll
                for (int d = 0; d < 2; d++)
                    #pragma unroll
                    for (int e = 0; e < 2; e++) acc[a][b][c][d][e] = 0.0f;

    const float* in_n = in + (size_t)n * C_in * H * W;
    for (int ic0 = 0; ic0 < C_in; ic0 += IC_BLK) {
        __syncthreads();
        for (int e = tid; e < IC_BLK * 45; e += 256) {
            int ic = e / 45; int rem = e - ic * 45;
            int r = rem / 9; int cc = rem - r * 9;
            int gy = y0 + r, gx = x0 + cc;
            float v = 0.0f;
            if (gy < H && gx < W) v = in_n[((size_t)(ic0 + ic) * H + gy) * W + gx];
            s_in[ic][r][cc] = v;
        }
        for (int e = tid; e < IC_BLK * 576; e += 256) {
            int ic = e / 576; int rem = e - ic * 576;
            int oc = rem / 9; int k = rem - oc * 9;
            s_w[ic][oc][k] = w[((size_t)(ic0 + ic) * C_out + oc0 + oc) * 9 + k];
        }
        __syncthreads();
        #pragma unroll 1
        for (int ic = 0; ic < IC_BLK; ic++) {
            float I[3][3];
            #pragma unroll
            for (int r = 0; r < 3; r++)
                #pragma unroll
                for (int c = 0; c < 3; c++)
                    I[r][c] = s_in[ic][(qr << 1) + r][(qc << 1) + c];
            #pragma unroll
            for (int o2 = 0; o2 < 2; o2++) {
                const float* wp_ = &s_w[ic][(ocg << 1) + o2][0];
                float W0 = wp_[0], W1 = wp_[1], W2 = wp_[2];
                float W3 = wp_[3], W4 = wp_[4], W5 = wp_[5];
                float W6 = wp_[6], W7 = wp_[7], W8 = wp_[8];
                #pragma unroll
                for (int qy = 0; qy < 2; qy++)
                    #pragma unroll
                    for (int qx = 0; qx < 2; qx++) {
                        float a00 = I[qy][qx],     a01 = I[qy][qx + 1];
                        float a10 = I[qy + 1][qx], a11 = I[qy + 1][qx + 1];
                        acc[o2][qy][qx][0][0] = fmaf(W4, a00, acc[o2][qy][qx][0][0]);
                        acc[o2][qy][qx][0][1] = fmaf(W5, a00, fmaf(W3, a01, acc[o2][qy][qx][0][1]));
                        acc[o2][qy][qx][1][0] = fmaf(W7, a00, fmaf(W1, a10, acc[o2][qy][qx][1][0]));
                        acc[o2][qy][qx][1][1] = fmaf(W8, a00, fmaf(W6, a01,
                                                fmaf(W2, a10, fmaf(W0, a11, acc[o2][qy][qx][1][1]))));
                    }
            }
        }
    }
    int OH = H << 1, OW = W << 1;
    #pragma unroll
    for (int o2 = 0; o2 < 2; o2++) {
        int oc = oc0 + (ocg << 1) + o2;
        float bv = bias[oc];
        float* out_c = out + ((size_t)n * C_out + oc) * OH * OW;
        #pragma unroll
        for (int qy = 0; qy < 2; qy++)
            #pragma unroll
            for (int qx = 0; qx < 2; qx++)
                #pragma unroll
                for (int dy = 0; dy < 2; dy++)
                    #pragma unroll
                    for (int dx = 0; dx < 2; dx++) {
                        int oy = ((y0 + (qr << 1) + qy) << 1) + dy;
                        int ox = ((x0 + (qc << 1) + qx) << 1) + dx;
                        out_c[(size_t)oy * OW + ox] =
                            fmaxf(acc[o2][qy][qx][dy][dx] + bv, 0.0f);
                    }
    }
}

// ---------------------------------------------------------------------------
// Output conv: C_in=128 -> 3, 256x256, tanh. One block per (n, row).
// ---------------------------------------------------------------------------
__global__ __launch_bounds__(256) void convWo_kernel(
    const float* __restrict__ in, const float* __restrict__ w,
    const float* __restrict__ bias, float* __restrict__ out)
{
    __shared__ float s_w[3456];            // 3 * 128 * 9, same flat layout as gmem
    __shared__ float s_in[8][3][258];
    int n = blockIdx.x >> 8;
    int y = blockIdx.x & 255;
    int tid = threadIdx.x;                 // one output column each
    for (int e = tid; e < 3456; e += 256) s_w[e] = w[e];
    float acc0 = bias[0], acc1 = bias[1], acc2 = bias[2];
    const float* in_n = in + (size_t)n * 128 * 65536;
    for (int ic0 = 0; ic0 < 128; ic0 += 8) {
        __syncthreads();
        for (int e = tid; e < 8 * 774; e += 256) {
            int ic = e / 774; int rem = e - ic * 774;
            int r = rem / 258; int cc = rem - r * 258;
            int gy = y - 1 + r, gx = cc - 1;
            float v = 0.0f;
            if ((unsigned)gy < 256u && (unsigned)gx < 256u)
                v = in_n[(size_t)(ic0 + ic) * 65536 + gy * 256 + gx];
            s_in[ic][r][cc] = v;
        }
        __syncthreads();
        #pragma unroll 1
        for (int ic = 0; ic < 8; ic++) {
            #pragma unroll
            for (int ky = 0; ky < 3; ky++)
                #pragma unroll
                for (int kx = 0; kx < 3; kx++) {
                    float iv = s_in[ic][ky][tid + kx];
                    int wi = (ic0 + ic) * 9 + ky * 3 + kx;
                    acc0 = fmaf(iv, s_w[wi], acc0);
                    acc1 = fmaf(iv, s_w[1152 + wi], acc1);
                    acc2 = fmaf(iv, s_w[2304 + wi], acc2);
                }
        }
    }
    size_t o = (size_t)n * 3 * 65536 + (size_t)y * 256 + tid;
    out[o]          = tanhf(acc0);
    out[o + 65536]  = tanhf(acc1);
    out[o + 131072] = tanhf(acc2);
}

// ---------------------------------------------------------------------------
// Host orchestration
// ---------------------------------------------------------------------------
static void conv_launch(const float* in, const float* w, const float* b, float* out,
                        int C_in, int C_out, int H, int W, int relu)
{
    dim3 grid((H / 8) * (W / 16), C_out / 64, 8);
    if (C_in % 8 == 0)
        conv3x3_kernel<8><<<grid, 256>>>(in, w, b, out, C_in, C_out, H, W, relu);
    else
        conv3x3_kernel<4><<<grid, 256>>>(in, w, b, out, C_in, C_out, H, W, relu);
}

static void deconv_launch(const float* in, const float* w, const float* b, float* out,
                          int C_in, int C_out, int H, int W)
{
    dim3 grid((H / 4) * (W / 8), C_out / 64, 8);
    deconv3x3s2_kernel<8><<<grid, 256>>>(in, w, b, out, C_in, C_out, H, W);
}

extern "C" void kernel_launch(void* const* d_in, const int* in_sizes, int n_in,
                              void* d_out, int out_size)
{
    const float* x   = (const float*)d_in[0];
    const float* We0 = (const float*)d_in[1];
    const float* be0 = (const float*)d_in[2];
    const float* We1 = (const float*)d_in[3];
    const float* be1 = (const float*)d_in[4];
    const float* Wi  = (const float*)d_in[5];
    const float* bi  = (const float*)d_in[6];
    const float* Wd1 = (const float*)d_in[7];
    const float* bd1 = (const float*)d_in[8];
    const float* Wc1 = (const float*)d_in[9];
    const float* bc1 = (const float*)d_in[10];
    const float* Wd2 = (const float*)d_in[11];
    const float* bd2 = (const float*)d_in[12];
    const float* Wc2 = (const float*)d_in[13];
    const float* bc2 = (const float*)d_in[14];
    const float* Wd3 = (const float*)d_in[15];
    const float* bd3 = (const float*)d_in[16];
    const float* Wc3 = (const float*)d_in[17];
    const float* bc3 = (const float*)d_in[18];
    const float* Wo  = (const float*)d_in[19];
    const float* bo  = (const float*)d_in[20];
    float* out = (float*)d_out;

    float *bufA, *bufB, *routed;
    cudaGetSymbolAddress((void**)&bufA, g_bufA);
    cudaGetSymbolAddress((void**)&bufB, g_bufB);
    cudaGetSymbolAddress((void**)&routed, g_routed);

    encoder_kernel<<<160, 256>>>(x, We0, be0, We1, be1);
    entropy_kernel<<<2048, 256>>>(x);
    median_kernel<<<1, 1024>>>();
    int write_aux = (out_size >= OUT_FULL) ? 1 : 0;
    route_kernel<<<128, 256>>>(out, write_aux);

    conv_launch(routed, Wi, bi, bufA, 4, 256, 32, 32, /*relu=*/0);     // h0  [8,256,32,32]
    deconv_launch(bufA, Wd1, bd1, bufB, 256, 256, 32, 32);             // t1  [8,256,64,64]
    conv_launch(bufB, Wc1, bc1, bufA, 256, 256, 64, 64, 1);            // h1
    deconv_launch(bufA, Wd2, bd2, bufB, 256, 128, 64, 64);             // t2  [8,128,128,128]
    conv_launch(bufB, Wc2, bc2, bufA, 128, 128, 128, 128, 1);          // h2
    deconv_launch(bufA, Wd3, bd3, bufB, 128, 128, 128, 128);           // t3  [8,128,256,256]
    conv_launch(bufB, Wc3, bc3, bufA, 128, 128, 256, 256, 1);          // h3
    convWo_kernel<<<2048, 256>>>(bufA, Wo, bo, out);                   // rec
}

// round 2
// speedup vs baseline: 1.1040x; 1.1040x over previous
#include <cuda_runtime.h>
#include <math.h>

typedef unsigned long long ull;

// ---------------------------------------------------------------------------
// Packed f32x2 helpers (Blackwell sm_103a)
// ---------------------------------------------------------------------------
__device__ __forceinline__ ull pk2(float lo, float hi) {
    ull r; asm("mov.b64 %0, {%1, %2};" : "=l"(r) : "f"(lo), "f"(hi)); return r;
}
__device__ __forceinline__ ull bc2(float v) {
    ull r; asm("mov.b64 %0, {%1, %1};" : "=l"(r) : "f"(v)); return r;
}
__device__ __forceinline__ void fma2(ull& d, ull a, ull b) {
    asm("fma.rn.f32x2 %0, %1, %2, %0;" : "+l"(d) : "l"(a), "l"(b));
}
__device__ __forceinline__ void up2(float& lo, float& hi, ull v) {
    asm("mov.b64 {%0, %1}, %2;" : "=f"(lo), "=f"(hi) : "l"(v));
}

// ---------------------------------------------------------------------------
// Scratch (device globals — no allocations allowed)
// ---------------------------------------------------------------------------
__device__ float g_bufA[67108864];   // 256 MB ping
__device__ float g_bufB[67108864];   // 256 MB pong
__device__ float g_latf[32768];      // lat_fine  [8,4,32,32]
__device__ float g_latc[8192];       // lat_coarse[8,4,16,16]
__device__ float g_ent[2048];        // entropy   [8,16,16]
__device__ float g_routed[32768];    // routed    [8,4,32,32]
__device__ float g_thr;

// Output layout (flattened tuple): rec | routed | grain | ent
#define OFF_ROUTED 1572864
#define OFF_GRAIN  1605632
#define OFF_ENT    1607680
#define OUT_FULL   1609728

// ---------------------------------------------------------------------------
// Encoder: two tiny strided 3x3 convs (stride 8 and 16, pad 1), C_in=3, C_out=4
// ---------------------------------------------------------------------------
__global__ void encoder_kernel(const float* __restrict__ x,
                               const float* __restrict__ We0, const float* __restrict__ be0,
                               const float* __restrict__ We1, const float* __restrict__ be1)
{
    int idx = blockIdx.x * blockDim.x + threadIdx.x;
    if (idx < 32768) {
        int n = idx >> 12, c = (idx >> 10) & 3, oy = (idx >> 5) & 31, ox = idx & 31;
        float acc = be0[c];
        for (int ic = 0; ic < 3; ic++)
            for (int ky = 0; ky < 3; ky++) {
                int iy = oy * 8 - 1 + ky;
                if ((unsigned)iy >= 256u) continue;
                for (int kx = 0; kx < 3; kx++) {
                    int ix = ox * 8 - 1 + kx;
                    if ((unsigned)ix >= 256u) continue;
                    acc += x[((n * 3 + ic) * 256 + iy) * 256 + ix] *
                           We0[((c * 3 + ic) * 3 + ky) * 3 + kx];
                }
            }
        g_latf[idx] = acc;
    } else if (idx < 40960) {
        int i2 = idx - 32768;
        int n = i2 >> 10, c = (i2 >> 8) & 3, oy = (i2 >> 4) & 15, ox = i2 & 15;
        float acc = be1[c];
        for (int ic = 0; ic < 3; ic++)
            for (int ky = 0; ky < 3; ky++) {
                int iy = oy * 16 - 1 + ky;
                if ((unsigned)iy >= 256u) continue;
                for (int kx = 0; kx < 3; kx++) {
                    int ix = ox * 16 - 1 + kx;
                    if ((unsigned)ix >= 256u) continue;
                    acc += x[((n * 3 + ic) * 256 + iy) * 256 + ix] *
                           We1[((c * 3 + ic) * 3 + ky) * 3 + kx];
                }
            }
        g_latc[i2] = acc;
    }
}

// ---------------------------------------------------------------------------
// Entropy map: one block per 16x16 patch. Gray -> sort -> windowed KDE -> H.
// ---------------------------------------------------------------------------
__global__ void entropy_kernel(const float* __restrict__ x)
{
    __shared__ float g[256];
    __shared__ float red[256];
    int bid = blockIdx.x;                       // b*256 + hp*16 + wp
    int b = bid >> 8, hp = (bid >> 4) & 15, wp = bid & 15;
    int tid = threadIdx.x;
    int py = tid >> 4, px = tid & 15;
    int gy = hp * 16 + py, gx = wp * 16 + px;
    const float* xb = x + (size_t)b * 3 * 65536;
    float gr = 0.299f * xb[gy * 256 + gx]
             + 0.587f * xb[65536 + gy * 256 + gx]
             + 0.114f * xb[131072 + gy * 256 + gx];
    g[tid] = gr;
    __syncthreads();

    for (int k = 2; k <= 256; k <<= 1)
        for (int j = k >> 1; j > 0; j >>= 1) {
            int ixj = tid ^ j;
            if (ixj > tid) {
                float a = g[tid], c2 = g[ixj];
                bool up = (tid & k) == 0;
                if ((a > c2) == up) { g[tid] = c2; g[ixj] = a; }
            }
            __syncthreads();
        }

    float vb = tid * (1.0f / 255.0f);
    const float R = 0.0945f;
    float loV = vb - R, hiV = vb + R;
    int lo = 0, hi = 256;
    while (lo < hi) { int m = (lo + hi) >> 1; if (g[m] < loV) lo = m + 1; else hi = m; }
    int s0 = lo;
    lo = s0; hi = 256;
    while (lo < hi) { int m = (lo + hi) >> 1; if (g[m] <= hiV) lo = m + 1; else hi = m; }
    int s1 = lo;
    float S = 0.0f;
    for (int i = s0; i < s1; i++) {
        float d = (g[i] - vb) * 100.0f;
        S += expf(-0.5f * d * d);
    }
    red[tid] = S;
    __syncthreads();
    for (int st = 128; st > 0; st >>= 1) { if (tid < st) red[tid] += red[tid + st]; __syncthreads(); }
    float T = red[0];
    __syncthreads();
    float p = S / T;
    p = fmaxf(p, 1e-10f);
    red[tid] = p * log2f(p);
    __syncthreads();
    for (int st = 128; st > 0; st >>= 1) { if (tid < st) red[tid] += red[tid + st]; __syncthreads(); }
    if (tid == 0) g_ent[bid] = -red[0];
}

// ---------------------------------------------------------------------------
// Median of 2048 entropies (jnp.quantile q=0.5): single-block bitonic.
// ---------------------------------------------------------------------------
__global__ void median_kernel()
{
    __shared__ float s[2048];
    int tid = threadIdx.x;      // 1024 threads
    s[tid] = g_ent[tid];
    s[tid + 1024] = g_ent[tid + 1024];
    __syncthreads();
    for (int k = 2; k <= 2048; k <<= 1)
        for (int j = k >> 1; j > 0; j >>= 1) {
            for (int base = 0; base < 2048; base += 1024) {
                int i = base + tid, ixj = i ^ j;
                if (ixj > i) {
                    float a = s[i], c2 = s[ixj];
                    bool up = (i & k) == 0;
                    if ((a > c2) == up) { s[i] = c2; s[ixj] = a; }
                }
            }
            __syncthreads();
        }
    if (tid == 0) g_thr = 0.5f * (s[1023] + s[1024]);
}

// ---------------------------------------------------------------------------
// Routing + aux outputs
// ---------------------------------------------------------------------------
__global__ void route_kernel(float* __restrict__ out, int write_aux)
{
    int i = blockIdx.x * blockDim.x + threadIdx.x;
    if (i >= 32768) return;
    float thr = g_thr;
    int n = i >> 12, c = (i >> 10) & 3, y = (i >> 5) & 31, xx = i & 31;
    int hp = y >> 1, wp = xx >> 1;
    float e = g_ent[n * 256 + hp * 16 + wp];
    float v = (e > thr) ? g_latf[i]
                        : g_latc[((n * 4 + c) * 16 + hp) * 16 + wp];
    g_routed[i] = v;
    if (write_aux) {
        out[OFF_ROUTED + i] = v;
        if (i < 2048) {
            float ev = g_ent[i];
            out[OFF_GRAIN + i] = (ev > thr) ? 1.0f : 0.0f;
            out[OFF_ENT + i] = ev;
        }
    }
}

// ---------------------------------------------------------------------------
// 3x3 stride-1 pad-1 conv, NCHW, packed f32x2. Block: 64 oc x (16x16) px,
// 256 threads, per-thread 4 oc x 4x4 px (32 f32x2 acc). Weights in smem
// pre-duplicated (w,w); inputs packed over column pairs.
// ---------------------------------------------------------------------------
template<int IC_BLK>
__global__ __launch_bounds__(256, 2) void conv3x3_kernel(
    const float* __restrict__ in, const float* __restrict__ w,
    const float* __restrict__ bias, float* __restrict__ out,
    int C_in, int C_out, int H, int W, int do_relu)
{
    __shared__ __align__(16) float s_in[IC_BLK][18][20];
    __shared__ ull s_w2[IC_BLK][9][64];
    int tiles_x = W >> 4;
    int ty = blockIdx.x / tiles_x, tx = blockIdx.x - ty * tiles_x;
    int oc0 = blockIdx.y << 6;
    int n = blockIdx.z;
    int y0 = ty << 4, x0 = tx << 4;
    int tid = threadIdx.x;
    int ocg = tid >> 4, pxg = tid & 15;
    int pr4 = (pxg >> 2) << 2, pc4 = (pxg & 3) << 2;

    ull acc[4][4][2];
    #pragma unroll
    for (int o = 0; o < 4; o++)
        #pragma unroll
        for (int r = 0; r < 4; r++) { acc[o][r][0] = 0ull; acc[o][r][1] = 0ull; }

    const float* in_n = in + (size_t)n * C_in * H * W;
    for (int ic0 = 0; ic0 < C_in; ic0 += IC_BLK) {
        __syncthreads();
        for (int e = tid; e < IC_BLK * 324; e += 256) {
            int ic = e / 324; int rem = e - ic * 324;
            int r = rem / 18; int cc = rem - r * 18;
            int gy = y0 - 1 + r, gx = x0 - 1 + cc;
            float v = 0.0f;
            if ((unsigned)gy < (unsigned)H && (unsigned)gx < (unsigned)W)
                v = in_n[((size_t)(ic0 + ic) * H + gy) * W + gx];
            s_in[ic][r][cc] = v;
        }
        for (int e = tid; e < IC_BLK * 576; e += 256) {
            int ic = e / 576; int rem = e - ic * 576;
            int k = rem >> 6; int oc = rem & 63;
            float v = w[((size_t)(oc0 + oc) * C_in + ic0 + ic) * 9 + k];
            s_w2[ic][k][oc] = bc2(v);
        }
        __syncthreads();
        #pragma unroll 1
        for (int ic = 0; ic < IC_BLK; ic++) {
            #pragma unroll
            for (int ky = 0; ky < 3; ky++) {
                ull w2[3][4];
                #pragma unroll
                for (int kx = 0; kx < 3; kx++)
                    #pragma unroll
                    for (int o = 0; o < 4; o++)
                        w2[kx][o] = s_w2[ic][ky * 3 + kx][(ocg << 2) + o];
                #pragma unroll
                for (int r = 0; r < 4; r++) {
                    const float* rp = &s_in[ic][pr4 + r + ky][pc4];
                    float4 v4 = *(const float4*)rp;
                    float2 v2 = *(const float2*)(rp + 4);
                    ull P0 = pk2(v4.x, v4.y);
                    ull P1 = pk2(v4.y, v4.z);
                    ull P2 = pk2(v4.z, v4.w);
                    ull P3 = pk2(v4.w, v2.x);
                    ull P4 = pk2(v2.x, v2.y);
                    #pragma unroll
                    for (int o = 0; o < 4; o++) {
                        fma2(acc[o][r][0], w2[0][o], P0);
                        fma2(acc[o][r][1], w2[0][o], P2);
                        fma2(acc[o][r][0], w2[1][o], P1);
                        fma2(acc[o][r][1], w2[1][o], P3);
                        fma2(acc[o][r][0], w2[2][o], P2);
                        fma2(acc[o][r][1], w2[2][o], P4);
                    }
                }
            }
        }
    }
    float* out_n = out + ((size_t)n * C_out + oc0) * H * W;
    #pragma unroll
    for (int o = 0; o < 4; o++) {
        int oc = (ocg << 2) + o;
        float bv = bias[oc0 + oc];
        #pragma unroll
        for (int r = 0; r < 4; r++) {
            float f0, f1, f2, f3;
            up2(f0, f1, acc[o][r][0]);
            up2(f2, f3, acc[o][r][1]);
            f0 += bv; f1 += bv; f2 += bv; f3 += bv;
            if (do_relu) {
                f0 = fmaxf(f0, 0.0f); f1 = fmaxf(f1, 0.0f);
                f2 = fmaxf(f2, 0.0f); f3 = fmaxf(f3, 0.0f);
            }
            *(float4*)&out_n[((size_t)oc * H + y0 + pr4 + r) * W + x0 + pc4] =
                make_float4(f0, f1, f2, f3);
        }
    }
}

// ---------------------------------------------------------------------------
// ConvTranspose2d k3 s2 p1 op1, packed over adjacent-oc pairs.
// Block: input tile 4x16 -> output 8x32, 64 oc. Thread: 4 oc x one 2x2 input
// quad (-> 4x4 output px): acc 2 oc-pairs x 16 px = 32 f32x2.
// ---------------------------------------------------------------------------
template<int IC_BLK>
__global__ __launch_bounds__(256, 2) void deconv3x3s2_kernel(
    const float* __restrict__ in, const float* __restrict__ w,
    const float* __restrict__ bias, float* __restrict__ out,
    int C_in, int C_out, int H, int W)   // input dims; output is 2H x 2W
{
    __shared__ __align__(16) float s_in[IC_BLK][5][18];
    __shared__ __align__(16) float s_w[IC_BLK][9][64];
    int tiles_x = W >> 4;
    int ty = blockIdx.x / tiles_x, tx = blockIdx.x - ty * tiles_x;
    int oc0 = blockIdx.y << 6;
    int n = blockIdx.z;
    int y0 = ty << 2, x0 = tx << 4;
    int tid = threadIdx.x;
    int ocg = tid >> 4, qg = tid & 15;
    int qr2 = (qg >> 3) << 1, qc2 = (qg & 7) << 1;

    ull acc[2][2][2][2][2];               // [ocpair][qy][qx][dy][dx]
    #pragma unroll
    for (int p = 0; p < 2; p++)
        #pragma unroll
        for (int a = 0; a < 2; a++)
            #pragma unroll
            for (int b = 0; b < 2; b++)
                #pragma unroll
                for (int c = 0; c < 2; c++) {
                    acc[p][a][b][c][0] = 0ull; acc[p][a][b][c][1] = 0ull;
                }

    const float* in_n = in + (size_t)n * C_in * H * W;
    for (int ic0 = 0; ic0 < C_in; ic0 += IC_BLK) {
        __syncthreads();
        for (int e = tid; e < IC_BLK * 85; e += 256) {
            int ic = e / 85; int rem = e - ic * 85;
            int r = rem / 17; int cc = rem - r * 17;
            int gy = y0 + r, gx = x0 + cc;
            float v = 0.0f;
            if (gy < H && gx < W) v = in_n[((size_t)(ic0 + ic) * H + gy) * W + gx];
            s_in[ic][r][cc] = v;
        }
        for (int e = tid; e < IC_BLK * 576; e += 256) {
            int ic = e / 576; int rem = e - ic * 576;
            int k = rem / 64; int oc = rem & 63;
            s_w[ic][k][oc] = w[((size_t)(ic0 + ic) * C_out + oc0 + oc) * 9 + k];
        }
        __syncthreads();
        #pragma unroll 1
        for (int ic = 0; ic < IC_BLK; ic++) {
            ull Ib[3][3];
            #pragma unroll
            for (int r = 0; r < 3; r++) {
                const float* rp = &s_in[ic][qr2 + r][qc2];
                float2 v2 = *(const float2*)rp;
                float vx = rp[2];
                Ib[r][0] = bc2(v2.x); Ib[r][1] = bc2(v2.y); Ib[r][2] = bc2(vx);
            }
            #pragma unroll
            for (int p = 0; p < 2; p++) {
                ull Wk[9];
                #pragma unroll
                for (int k = 0; k < 9; k++)
                    Wk[k] = *(const ull*)&s_w[ic][k][(ocg << 2) + (p << 1)];
                #pragma unroll
                for (int qy = 0; qy < 2; qy++)
                    #pragma unroll
                    for (int qx = 0; qx < 2; qx++) {
                        ull a00 = Ib[qy][qx],     a01 = Ib[qy][qx + 1];
                        ull a10 = Ib[qy + 1][qx], a11 = Ib[qy + 1][qx + 1];
                        fma2(acc[p][qy][qx][0][0], Wk[4], a00);
                        fma2(acc[p][qy][qx][0][1], Wk[5], a00);
                        fma2(acc[p][qy][qx][0][1], Wk[3], a01);
                        fma2(acc[p][qy][qx][1][0], Wk[7], a00);
                        fma2(acc[p][qy][qx][1][0], Wk[1], a10);
                        fma2(acc[p][qy][qx][1][1], Wk[8], a00);
                        fma2(acc[p][qy][qx][1][1], Wk[6], a01);
                        fma2(acc[p][qy][qx][1][1], Wk[2], a10);
                        fma2(acc[p][qy][qx][1][1], Wk[0], a11);
                    }
            }
        }
    }
    int OH = H << 1, OW = W << 1;
    #pragma unroll
    for (int p = 0; p < 2; p++) {
        int oc_lo = oc0 + (ocg << 2) + (p << 1);
        float b_lo = bias[oc_lo], b_hi = bias[oc_lo + 1];
        float* out_lo = out + ((size_t)n * C_out + oc_lo) * OH * OW;
        float* out_hi = out_lo + (size_t)OH * OW;
        #pragma unroll
        for (int qy = 0; qy < 2; qy++)
            #pragma unroll
            for (int qx = 0; qx < 2; qx++) {
                int oxb = (x0 + qc2 + qx) << 1;
                #pragma unroll
                for (int dy = 0; dy < 2; dy++) {
                    int oy = ((y0 + qr2 + qy) << 1) + dy;
                    float l0, h0, l1, h1;
                    up2(l0, h0, acc[p][qy][qx][dy][0]);
                    up2(l1, h1, acc[p][qy][qx][dy][1]);
                    *(float2*)&out_lo[(size_t)oy * OW + oxb] =
                        make_float2(fmaxf(l0 + b_lo, 0.0f), fmaxf(l1 + b_lo, 0.0f));
                    *(float2*)&out_hi[(size_t)oy * OW + oxb] =
                        make_float2(fmaxf(h0 + b_hi, 0.0f), fmaxf(h1 + b_hi, 0.0f));
                }
            }
    }
}

// ---------------------------------------------------------------------------
// Output conv: 128 -> 3, 256x256, tanh. Block covers (n, 8 rows); thread:
// 2 rows x 4 cols x 3 ch, packed over column pairs.
// ---------------------------------------------------------------------------
__global__ __launch_bounds__(256) void convWo_kernel(
    const float* __restrict__ in, const float* __restrict__ w,
    const float* __restrict__ bias, float* __restrict__ out)
{
    __shared__ float s_w[3456];            // 3 * 128 * 9, flat gmem layout
    __shared__ __align__(16) float s_in[2][10][260];
    int n = blockIdx.x >> 5;
    int y0 = (blockIdx.x & 31) << 3;
    int tid = threadIdx.x;
    int rowg = tid >> 6;                   // 0..3 -> rows y0 + rowg*2 + {0,1}
    int c4 = (tid & 63) << 2;              // cols c4..c4+3
    for (int e = tid; e < 3456; e += 256) s_w[e] = w[e];

    ull acc[3][2][2];                      // [ch][r][colpair]
    #pragma unroll
    for (int ch = 0; ch < 3; ch++)
        #pragma unroll
        for (int r = 0; r < 2; r++) { acc[ch][r][0] = 0ull; acc[ch][r][1] = 0ull; }

    const float* in_n = in + (size_t)n * 128 * 65536;
    for (int ic0 = 0; ic0 < 128; ic0 += 2) {
        __syncthreads();
        for (int e = tid; e < 2 * 2580; e += 256) {
            int ic = e / 2580; int rem = e - ic * 2580;
            int rr = rem / 258; int cc = rem - rr * 258;
            int gy = y0 - 1 + rr, gx = cc - 1;
            float v = 0.0f;
            if ((unsigned)gy < 256u && (unsigned)gx < 256u)
                v = in_n[(size_t)(ic0 + ic) * 65536 + gy * 256 + gx];
            s_in[ic][rr][cc] = v;
        }
        __syncthreads();
        #pragma unroll
        for (int ic = 0; ic < 2; ic++) {
            #pragma unroll
            for (int ky = 0; ky < 3; ky++) {
                ull P[2][5];
                #pragma unroll
                for (int r = 0; r < 2; r++) {
                    const float* rp = &s_in[ic][(rowg << 1) + r + ky][c4];
                    float4 v4 = *(const float4*)rp;
                    float2 v2 = *(const float2*)(rp + 4);
                    P[r][0] = pk2(v4.x, v4.y);
                    P[r][1] = pk2(v4.y, v4.z);
                    P[r][2] = pk2(v4.z, v4.w);
                    P[r][3] = pk2(v4.w, v2.x);
                    P[r][4] = pk2(v2.x, v2.y);
                }
                #pragma unroll
                for (int kx = 0; kx < 3; kx++)
                    #pragma unroll
                    for (int ch = 0; ch < 3; ch++) {
                        ull wb = bc2(s_w[ch * 1152 + (ic0 + ic) * 9 + ky * 3 + kx]);
                        #pragma unroll
                        for (int r = 0; r < 2; r++) {
                            fma2(acc[ch][r][0], wb, P[r][kx]);
                            fma2(acc[ch][r][1], wb, P[r][kx + 2]);
                        }
                    }
            }
        }
    }
    #pragma unroll
    for (int ch = 0; ch < 3; ch++) {
        float bv = bias[ch];
        #pragma unroll
        for (int r = 0; r < 2; r++) {
            int y = y0 + (rowg << 1) + r;
            float f0, f1, f2, f3;
            up2(f0, f1, acc[ch][r][0]);
            up2(f2, f3, acc[ch][r][1]);
            *(float4*)&out[((size_t)(n * 3 + ch) << 16) + y * 256 + c4] =
                make_float4(tanhf(f0 + bv), tanhf(f1 + bv),
                            tanhf(f2 + bv), tanhf(f3 + bv));
        }
    }
}

// ---------------------------------------------------------------------------
// Host orchestration
// ---------------------------------------------------------------------------
static void conv_launch(const float* in, const float* w, const float* b, float* out,
                        int C_in, int C_out, int H, int W, int relu)
{
    dim3 grid((H / 16) * (W / 16), C_out / 64, 8);
    conv3x3_kernel<4><<<grid, 256>>>(in, w, b, out, C_in, C_out, H, W, relu);
}

static void deconv_launch(const float* in, const float* w, const float* b, float* out,
                          int C_in, int C_out, int H, int W)
{
    dim3 grid((H / 4) * (W / 16), C_out / 64, 8);
    deconv3x3s2_kernel<8><<<grid, 256>>>(in, w, b, out, C_in, C_out, H, W);
}

extern "C" void kernel_launch(void* const* d_in, const int* in_sizes, int n_in,
                              void* d_out, int out_size)
{
    const float* x   = (const float*)d_in[0];
    const float* We0 = (const float*)d_in[1];
    const float* be0 = (const float*)d_in[2];
    const float* We1 = (const float*)d_in[3];
    const float* be1 = (const float*)d_in[4];
    const float* Wi  = (const float*)d_in[5];
    const float* bi  = (const float*)d_in[6];
    const float* Wd1 = (const float*)d_in[7];
    const float* bd1 = (const float*)d_in[8];
    const float* Wc1 = (const float*)d_in[9];
    const float* bc1 = (const float*)d_in[10];
    const float* Wd2 = (const float*)d_in[11];
    const float* bd2 = (const float*)d_in[12];
    const float* Wc2 = (const float*)d_in[13];
    const float* bc2_ = (const float*)d_in[14];
    const float* Wd3 = (const float*)d_in[15];
    const float* bd3 = (const float*)d_in[16];
    const float* Wc3 = (const float*)d_in[17];
    const float* bc3 = (const float*)d_in[18];
    const float* Wo  = (const float*)d_in[19];
    const float* bo  = (const float*)d_in[20];
    float* out = (float*)d_out;

    float *bufA, *bufB, *routed;
    cudaGetSymbolAddress((void**)&bufA, g_bufA);
    cudaGetSymbolAddress((void**)&bufB, g_bufB);
    cudaGetSymbolAddress((void**)&routed, g_routed);

    encoder_kernel<<<160, 256>>>(x, We0, be0, We1, be1);
    entropy_kernel<<<2048, 256>>>(x);
    median_kernel<<<1, 1024>>>();
    int write_aux = (out_size >= OUT_FULL) ? 1 : 0;
    route_kernel<<<128, 256>>>(out, write_aux);

    conv_launch(routed, Wi, bi, bufA, 4, 256, 32, 32, /*relu=*/0);     // h0  [8,256,32,32]
    deconv_launch(bufA, Wd1, bd1, bufB, 256, 256, 32, 32);             // t1  [8,256,64,64]
    conv_launch(bufB, Wc1, bc1, bufA, 256, 256, 64, 64, 1);            // h1
    deconv_launch(bufA, Wd2, bd2, bufB, 256, 128, 64, 64);             // t2  [8,128,128,128]
    conv_launch(bufB, Wc2, bc2_, bufA, 128, 128, 128, 128, 1);         // h2
    deconv_launch(bufA, Wd3, bd3, bufB, 128, 128, 128, 128);           // t3  [8,128,256,256]
    conv_launch(bufB, Wc3, bc3, bufA, 128, 128, 256, 256, 1);          // h3
    convWo_kernel<<<256, 256>>>(bufA, Wo, bo, out);                    // rec
}

// round 3
// speedup vs baseline: 1.1054x; 1.0013x over previous
#include <cuda_runtime.h>
#include <math.h>

typedef unsigned long long ull;

// ---------------------------------------------------------------------------
// Packed f32x2 helpers (Blackwell sm_103a)
// ---------------------------------------------------------------------------
__device__ __forceinline__ ull pk2(float lo, float hi) {
    ull r; asm("mov.b64 %0, {%1, %2};" : "=l"(r) : "f"(lo), "f"(hi)); return r;
}
__device__ __forceinline__ ull bc2(float v) {
    ull r; asm("mov.b64 %0, {%1, %1};" : "=l"(r) : "f"(v)); return r;
}
__device__ __forceinline__ void fma2(ull& d, ull a, ull b) {
    asm("fma.rn.f32x2 %0, %1, %2, %0;" : "+l"(d) : "l"(a), "l"(b));
}
__device__ __forceinline__ void up2(float& lo, float& hi, ull v) {
    asm("mov.b64 {%0, %1}, %2;" : "=f"(lo), "=f"(hi) : "l"(v));
}

// ---------------------------------------------------------------------------
// Scratch (device globals — no allocations allowed)
// ---------------------------------------------------------------------------
__device__ float g_bufA[67108864];   // 256 MB ping
__device__ float g_bufB[67108864];   // 256 MB pong
__device__ float g_latf[32768];      // lat_fine  [8,4,32,32]
__device__ float g_latc[8192];       // lat_coarse[8,4,16,16]
__device__ float g_ent[2048];        // entropy   [8,16,16]
__device__ float g_routed[32768];    // routed    [8,4,32,32]
__device__ float g_thr;

// Output layout (flattened tuple): rec | routed | grain | ent
#define OFF_ROUTED 1572864
#define OFF_GRAIN  1605632
#define OFF_ENT    1607680
#define OUT_FULL   1609728

// ---------------------------------------------------------------------------
// Encoder: two tiny strided 3x3 convs (stride 8 and 16, pad 1), C_in=3, C_out=4
// ---------------------------------------------------------------------------
__global__ void encoder_kernel(const float* __restrict__ x,
                               const float* __restrict__ We0, const float* __restrict__ be0,
                               const float* __restrict__ We1, const float* __restrict__ be1)
{
    int idx = blockIdx.x * blockDim.x + threadIdx.x;
    if (idx < 32768) {
        int n = idx >> 12, c = (idx >> 10) & 3, oy = (idx >> 5) & 31, ox = idx & 31;
        float acc = be0[c];
        for (int ic = 0; ic < 3; ic++)
            for (int ky = 0; ky < 3; ky++) {
                int iy = oy * 8 - 1 + ky;
                if ((unsigned)iy >= 256u) continue;
                for (int kx = 0; kx < 3; kx++) {
                    int ix = ox * 8 - 1 + kx;
                    if ((unsigned)ix >= 256u) continue;
                    acc += x[((n * 3 + ic) * 256 + iy) * 256 + ix] *
                           We0[((c * 3 + ic) * 3 + ky) * 3 + kx];
                }
            }
        g_latf[idx] = acc;
    } else if (idx < 40960) {
        int i2 = idx - 32768;
        int n = i2 >> 10, c = (i2 >> 8) & 3, oy = (i2 >> 4) & 15, ox = i2 & 15;
        float acc = be1[c];
        for (int ic = 0; ic < 3; ic++)
            for (int ky = 0; ky < 3; ky++) {
                int iy = oy * 16 - 1 + ky;
                if ((unsigned)iy >= 256u) continue;
                for (int kx = 0; kx < 3; kx++) {
                    int ix = ox * 16 - 1 + kx;
                    if ((unsigned)ix >= 256u) continue;
                    acc += x[((n * 3 + ic) * 256 + iy) * 256 + ix] *
                           We1[((c * 3 + ic) * 3 + ky) * 3 + kx];
                }
            }
        g_latc[i2] = acc;
    }
}

// ---------------------------------------------------------------------------
// Entropy map: one block per 16x16 patch. Gray -> sort -> windowed KDE -> H.
// ---------------------------------------------------------------------------
__global__ void entropy_kernel(const float* __restrict__ x)
{
    __shared__ float g[256];
    __shared__ float red[256];
    int bid = blockIdx.x;                       // b*256 + hp*16 + wp
    int b = bid >> 8, hp = (bid >> 4) & 15, wp = bid & 15;
    int tid = threadIdx.x;
    int py = tid >> 4, px = tid & 15;
    int gy = hp * 16 + py, gx = wp * 16 + px;
    const float* xb = x + (size_t)b * 3 * 65536;
    float gr = 0.299f * xb[gy * 256 + gx]
             + 0.587f * xb[65536 + gy * 256 + gx]
             + 0.114f * xb[131072 + gy * 256 + gx];
    g[tid] = gr;
    __syncthreads();

    for (int k = 2; k <= 256; k <<= 1)
        for (int j = k >> 1; j > 0; j >>= 1) {
            int ixj = tid ^ j;
            if (ixj > tid) {
                float a = g[tid], c2 = g[ixj];
                bool up = (tid & k) == 0;
                if ((a > c2) == up) { g[tid] = c2; g[ixj] = a; }
            }
            __syncthreads();
        }

    float vb = tid * (1.0f / 255.0f);
    const float R = 0.0945f;
    float loV = vb - R, hiV = vb + R;
    int lo = 0, hi = 256;
    while (lo < hi) { int m = (lo + hi) >> 1; if (g[m] < loV) lo = m + 1; else hi = m; }
    int s0 = lo;
    lo = s0; hi = 256;
    while (lo < hi) { int m = (lo + hi) >> 1; if (g[m] <= hiV) lo = m + 1; else hi = m; }
    int s1 = lo;
    float S = 0.0f;
    for (int i = s0; i < s1; i++) {
        float d = (g[i] - vb) * 100.0f;
        S += expf(-0.5f * d * d);
    }
    red[tid] = S;
    __syncthreads();
    for (int st = 128; st > 0; st >>= 1) { if (tid < st) red[tid] += red[tid + st]; __syncthreads(); }
    float T = red[0];
    __syncthreads();
    float p = S / T;
    p = fmaxf(p, 1e-10f);
    red[tid] = p * log2f(p);
    __syncthreads();
    for (int st = 128; st > 0; st >>= 1) { if (tid < st) red[tid] += red[tid + st]; __syncthreads(); }
    if (tid == 0) g_ent[bid] = -red[0];
}

// ---------------------------------------------------------------------------
// Median of 2048 entropies (jnp.quantile q=0.5): single-block bitonic.
// ---------------------------------------------------------------------------
__global__ void median_kernel()
{
    __shared__ float s[2048];
    int tid = threadIdx.x;      // 1024 threads
    s[tid] = g_ent[tid];
    s[tid + 1024] = g_ent[tid + 1024];
    __syncthreads();
    for (int k = 2; k <= 2048; k <<= 1)
        for (int j = k >> 1; j > 0; j >>= 1) {
            for (int base = 0; base < 2048; base += 1024) {
                int i = base + tid, ixj = i ^ j;
                if (ixj > i) {
                    float a = s[i], c2 = s[ixj];
                    bool up = (i & k) == 0;
                    if ((a > c2) == up) { s[i] = c2; s[ixj] = a; }
                }
            }
            __syncthreads();
        }
    if (tid == 0) g_thr = 0.5f * (s[1023] + s[1024]);
}

// ---------------------------------------------------------------------------
// Routing + aux outputs
// ---------------------------------------------------------------------------
__global__ void route_kernel(float* __restrict__ out, int write_aux)
{
    int i = blockIdx.x * blockDim.x + threadIdx.x;
    if (i >= 32768) return;
    float thr = g_thr;
    int n = i >> 12, c = (i >> 10) & 3, y = (i >> 5) & 31, xx = i & 31;
    int hp = y >> 1, wp = xx >> 1;
    float e = g_ent[n * 256 + hp * 16 + wp];
    float v = (e > thr) ? g_latf[i]
                        : g_latc[((n * 4 + c) * 16 + hp) * 16 + wp];
    g_routed[i] = v;
    if (write_aux) {
        out[OFF_ROUTED + i] = v;
        if (i < 2048) {
            float ev = g_ent[i];
            out[OFF_GRAIN + i] = (ev > thr) ? 1.0f : 0.0f;
            out[OFF_ENT + i] = ev;
        }
    }
}

// ---------------------------------------------------------------------------
// 3x3 stride-1 pad-1 conv, NCHW, packed f32x2. Block: 64 oc x (16x16) px,
// 256 threads, per-thread 4 oc x 4x4 px (32 f32x2 acc). Weights in smem
// pre-duplicated (w,w); inputs packed over column pairs.
// ---------------------------------------------------------------------------
template<int IC_BLK>
__global__ __launch_bounds__(256, 2) void conv3x3_kernel(
    const float* __restrict__ in, const float* __restrict__ w,
    const float* __restrict__ bias, float* __restrict__ out,
    int C_in, int C_out, int H, int W, int do_relu)
{
    __shared__ __align__(16) float s_in[IC_BLK][18][20];
    __shared__ ull s_w2[IC_BLK][9][64];
    int tiles_x = W >> 4;
    int ty = blockIdx.x / tiles_x, tx = blockIdx.x - ty * tiles_x;
    int oc0 = blockIdx.y << 6;
    int n = blockIdx.z;
    int y0 = ty << 4, x0 = tx << 4;
    int tid = threadIdx.x;
    int ocg = tid >> 4, pxg = tid & 15;
    int pr4 = (pxg >> 2) << 2, pc4 = (pxg & 3) << 2;

    ull acc[4][4][2];
    #pragma unroll
    for (int o = 0; o < 4; o++)
        #pragma unroll
        for (int r = 0; r < 4; r++) { acc[o][r][0] = 0ull; acc[o][r][1] = 0ull; }

    const float* in_n = in + (size_t)n * C_in * H * W;
    for (int ic0 = 0; ic0 < C_in; ic0 += IC_BLK) {
        __syncthreads();
        for (int e = tid; e < IC_BLK * 324; e += 256) {
            int ic = e / 324; int rem = e - ic * 324;
            int r = rem / 18; int cc = rem - r * 18;
            int gy = y0 - 1 + r, gx = x0 - 1 + cc;
            float v = 0.0f;
            if ((unsigned)gy < (unsigned)H && (unsigned)gx < (unsigned)W)
                v = in_n[((size_t)(ic0 + ic) * H + gy) * W + gx];
            s_in[ic][r][cc] = v;
        }
        for (int e = tid; e < IC_BLK * 576; e += 256) {
            int ic = e / 576; int rem = e - ic * 576;
            int k = rem >> 6; int oc = rem & 63;
            float v = w[((size_t)(oc0 + oc) * C_in + ic0 + ic) * 9 + k];
            s_w2[ic][k][oc] = bc2(v);
        }
        __syncthreads();
        #pragma unroll 1
        for (int ic = 0; ic < IC_BLK; ic++) {
            #pragma unroll
            for (int ky = 0; ky < 3; ky++) {
                ull w2[3][4];
                #pragma unroll
                for (int kx = 0; kx < 3; kx++)
                    #pragma unroll
                    for (int o = 0; o < 4; o++)
                        w2[kx][o] = s_w2[ic][ky * 3 + kx][(ocg << 2) + o];
                #pragma unroll
                for (int r = 0; r < 4; r++) {
                    const float* rp = &s_in[ic][pr4 + r + ky][pc4];
                    float4 v4 = *(const float4*)rp;
                    float2 v2 = *(const float2*)(rp + 4);
                    ull P0 = pk2(v4.x, v4.y);
                    ull P1 = pk2(v4.y, v4.z);
                    ull P2 = pk2(v4.z, v4.w);
                    ull P3 = pk2(v4.w, v2.x);
                    ull P4 = pk2(v2.x, v2.y);
                    #pragma unroll
                    for (int o = 0; o < 4; o++) {
                        fma2(acc[o][r][0], w2[0][o], P0);
                        fma2(acc[o][r][1], w2[0][o], P2);
                        fma2(acc[o][r][0], w2[1][o], P1);
                        fma2(acc[o][r][1], w2[1][o], P3);
                        fma2(acc[o][r][0], w2[2][o], P2);
                        fma2(acc[o][r][1], w2[2][o], P4);
                    }
                }
            }
        }
    }
    float* out_n = out + ((size_t)n * C_out + oc0) * H * W;
    #pragma unroll
    for (int o = 0; o < 4; o++) {
        int oc = (ocg << 2) + o;
        float bv = bias[oc0 + oc];
        #pragma unroll
        for (int r = 0; r < 4; r++) {
            float f0, f1, f2, f3;
            up2(f0, f1, acc[o][r][0]);
            up2(f2, f3, acc[o][r][1]);
            f0 += bv; f1 += bv; f2 += bv; f3 += bv;
            if (do_relu) {
                f0 = fmaxf(f0, 0.0f); f1 = fmaxf(f1, 0.0f);
                f2 = fmaxf(f2, 0.0f); f3 = fmaxf(f3, 0.0f);
            }
            *(float4*)&out_n[((size_t)oc * H + y0 + pr4 + r) * W + x0 + pc4] =
                make_float4(f0, f1, f2, f3);
        }
    }
}

// ---------------------------------------------------------------------------
// ConvTranspose2d k3 s2 p1 op1, packed over adjacent-oc pairs.
// Block: input tile 4x16 -> output 8x32, 64 oc. Thread: 4 oc x one 2x2 input
// quad (-> 4x4 output px): acc 2 oc-pairs x 16 px = 32 f32x2.
// ---------------------------------------------------------------------------
template<int IC_BLK>
__global__ __launch_bounds__(256, 2) void deconv3x3s2_kernel(
    const float* __restrict__ in, const float* __restrict__ w,
    const float* __restrict__ bias, float* __restrict__ out,
    int C_in, int C_out, int H, int W)   // input dims; output is 2H x 2W
{
    __shared__ __align__(16) float s_in[IC_BLK][5][18];
    __shared__ __align__(16) float s_w[IC_BLK][9][64];
    int tiles_x = W >> 4;
    int ty = blockIdx.x / tiles_x, tx = blockIdx.x - ty * tiles_x;
    int oc0 = blockIdx.y << 6;
    int n = blockIdx.z;
    int y0 = ty << 2, x0 = tx << 4;
    int tid = threadIdx.x;
    int ocg = tid >> 4, qg = tid & 15;
    int qr2 = (qg >> 3) << 1, qc2 = (qg & 7) << 1;

    ull acc[2][2][2][2][2];               // [ocpair][qy][qx][dy][dx]
    #pragma unroll
    for (int p = 0; p < 2; p++)
        #pragma unroll
        for (int a = 0; a < 2; a++)
            #pragma unroll
            for (int b = 0; b < 2; b++)
                #pragma unroll
                for (int c = 0; c < 2; c++) {
                    acc[p][a][b][c][0] = 0ull; acc[p][a][b][c][1] = 0ull;
                }

    const float* in_n = in + (size_t)n * C_in * H * W;
    for (int ic0 = 0; ic0 < C_in; ic0 += IC_BLK) {
        __syncthreads();
        for (int e = tid; e < IC_BLK * 85; e += 256) {
            int ic = e / 85; int rem = e - ic * 85;
            int r = rem / 17; int cc = rem - r * 17;
            int gy = y0 + r, gx = x0 + cc;
            float v = 0.0f;
            if (gy < H && gx < W) v = in_n[((size_t)(ic0 + ic) * H + gy) * W + gx];
            s_in[ic][r][cc] = v;
        }
        for (int e = tid; e < IC_BLK * 576; e += 256) {
            int ic = e / 576; int rem = e - ic * 576;
            int k = rem / 64; int oc = rem & 63;
            s_w[ic][k][oc] = w[((size_t)(ic0 + ic) * C_out + oc0 + oc) * 9 + k];
        }
        __syncthreads();
        #pragma unroll 1
        for (int ic = 0; ic < IC_BLK; ic++) {
            ull Ib[3][3];
            #pragma unroll
            for (int r = 0; r < 3; r++) {
                const float* rp = &s_in[ic][qr2 + r][qc2];
                float2 v2 = *(const float2*)rp;
                float vx = rp[2];
                Ib[r][0] = bc2(v2.x); Ib[r][1] = bc2(v2.y); Ib[r][2] = bc2(vx);
            }
            #pragma unroll
            for (int p = 0; p < 2; p++) {
                ull Wk[9];
                #pragma unroll
                for (int k = 0; k < 9; k++)
                    Wk[k] = *(const ull*)&s_w[ic][k][(ocg << 2) + (p << 1)];
                #pragma unroll
                for (int qy = 0; qy < 2; qy++)
                    #pragma unroll
                    for (int qx = 0; qx < 2; qx++) {
                        ull a00 = Ib[qy][qx],     a01 = Ib[qy][qx + 1];
                        ull a10 = Ib[qy + 1][qx], a11 = Ib[qy + 1][qx + 1];
                        fma2(acc[p][qy][qx][0][0], Wk[4], a00);
                        fma2(acc[p][qy][qx][0][1], Wk[5], a00);
                        fma2(acc[p][qy][qx][0][1], Wk[3], a01);
                        fma2(acc[p][qy][qx][1][0], Wk[7], a00);
                        fma2(acc[p][qy][qx][1][0], Wk[1], a10);
                        fma2(acc[p][qy][qx][1][1], Wk[8], a00);
                        fma2(acc[p][qy][qx][1][1], Wk[6], a01);
                        fma2(acc[p][qy][qx][1][1], Wk[2], a10);
                        fma2(acc[p][qy][qx][1][1], Wk[0], a11);
                    }
            }
        }
    }
    int OH = H << 1, OW = W << 1;
    #pragma unroll
    for (int p = 0; p < 2; p++) {
        int oc_lo = oc0 + (ocg << 2) + (p << 1);
        float b_lo = bias[oc_lo], b_hi = bias[oc_lo + 1];
        float* out_lo = out + ((size_t)n * C_out + oc_lo) * OH * OW;
        float* out_hi = out_lo + (size_t)OH * OW;
        #pragma unroll
        for (int qy = 0; qy < 2; qy++)
            #pragma unroll
            for (int qx = 0; qx < 2; qx++) {
                int oxb = (x0 + qc2 + qx) << 1;
                #pragma unroll
                for (int dy = 0; dy < 2; dy++) {
                    int oy = ((y0 + qr2 + qy) << 1) + dy;
                    float l0, h0, l1, h1;
                    up2(l0, h0, acc[p][qy][qx][dy][0]);
                    up2(l1, h1, acc[p][qy][qx][dy][1]);
                    *(float2*)&out_lo[(size_t)oy * OW + oxb] =
                        make_float2(fmaxf(l0 + b_lo, 0.0f), fmaxf(l1 + b_lo, 0.0f));
                    *(float2*)&out_hi[(size_t)oy * OW + oxb] =
                        make_float2(fmaxf(h0 + b_hi, 0.0f), fmaxf(h1 + b_hi, 0.0f));
                }
            }
    }
}

// ---------------------------------------------------------------------------
// Output conv: 128 -> 3, 256x256, tanh. Block covers (n, 8 rows); thread:
// 2 rows x 4 cols x 3 ch, packed over column pairs.
// ---------------------------------------------------------------------------
__global__ __launch_bounds__(256) void convWo_kernel(
    const float* __restrict__ in, const float* __restrict__ w,
    const float* __restrict__ bias, float* __restrict__ out)
{
    __shared__ float s_w[3456];            // 3 * 128 * 9, flat gmem layout
    __shared__ __align__(16) float s_in[2][10][260];
    int n = blockIdx.x >> 5;
    int y0 = (blockIdx.x & 31) << 3;
    int tid = threadIdx.x;
    int rowg = tid >> 6;                   // 0..3 -> rows y0 + rowg*2 + {0,1}
    int c4 = (tid & 63) << 2;              // cols c4..c4+3
    for (int e = tid; e < 3456; e += 256) s_w[e] = w[e];

    ull acc[3][2][2];                      // [ch][r][colpair]
    #pragma unroll
    for (int ch = 0; ch < 3; ch++)
        #pragma unroll
        for (int r = 0; r < 2; r++) { acc[ch][r][0] = 0ull; acc[ch][r][1] = 0ull; }

    const float* in_n = in + (size_t)n * 128 * 65536;
    for (int ic0 = 0; ic0 < 128; ic0 += 2) {
        __syncthreads();
        for (int e = tid; e < 2 * 2580; e += 256) {
            int ic = e / 2580; int rem = e - ic * 2580;
            int rr = rem / 258; int cc = rem - rr * 258;
            int gy = y0 - 1 + rr, gx = cc - 1;
            float v = 0.0f;
            if ((unsigned)gy < 256u && (unsigned)gx < 256u)
                v = in_n[(size_t)(ic0 + ic) * 65536 + gy * 256 + gx];
            s_in[ic][rr][cc] = v;
        }
        __syncthreads();
        #pragma unroll
        for (int ic = 0; ic < 2; ic++) {
            #pragma unroll
            for (int ky = 0; ky < 3; ky++) {
                ull P[2][5];
                #pragma unroll
                for (int r = 0; r < 2; r++) {
                    const float* rp = &s_in[ic][(rowg << 1) + r + ky][c4];
                    float4 v4 = *(const float4*)rp;
                    float2 v2 = *(const float2*)(rp + 4);
                    P[r][0] = pk2(v4.x, v4.y);
                    P[r][1] = pk2(v4.y, v4.z);
                    P[r][2] = pk2(v4.z, v4.w);
                    P[r][3] = pk2(v4.w, v2.x);
                    P[r][4] = pk2(v2.x, v2.y);
                }
                #pragma unroll
                for (int kx = 0; kx < 3; kx++)
                    #pragma unroll
                    for (int ch = 0; ch < 3; ch++) {
                        ull wb = bc2(s_w[ch * 1152 + (ic0 + ic) * 9 + ky * 3 + kx]);
                        #pragma unroll
                        for (int r = 0; r < 2; r++) {
                            fma2(acc[ch][r][0], wb, P[r][kx]);
                            fma2(acc[ch][r][1], wb, P[r][kx + 2]);
                        }
                    }
            }
        }
    }
    #pragma unroll
    for (int ch = 0; ch < 3; ch++) {
        float bv = bias[ch];
        #pragma unroll
        for (int r = 0; r < 2; r++) {
            int y = y0 + (rowg << 1) + r;
            float f0, f1, f2, f3;
            up2(f0, f1, acc[ch][r][0]);
            up2(f2, f3, acc[ch][r][1]);
            *(float4*)&out[((size_t)(n * 3 + ch) << 16) + y * 256 + c4] =
                make_float4(tanhf(f0 + bv), tanhf(f1 + bv),
                            tanhf(f2 + bv), tanhf(f3 + bv));
        }
    }
}

// ---------------------------------------------------------------------------
// Host orchestration
// ---------------------------------------------------------------------------
static void conv_launch(const float* in, const float* w, const float* b, float* out,
                        int C_in, int C_out, int H, int W, int relu)
{
    dim3 grid((H / 16) * (W / 16), C_out / 64, 8);
    conv3x3_kernel<4><<<grid, 256>>>(in, w, b, out, C_in, C_out, H, W, relu);
}

static void deconv_launch(const float* in, const float* w, const float* b, float* out,
                          int C_in, int C_out, int H, int W)
{
    dim3 grid((H / 4) * (W / 16), C_out / 64, 8);
    deconv3x3s2_kernel<8><<<grid, 256>>>(in, w, b, out, C_in, C_out, H, W);
}

extern "C" void kernel_launch(void* const* d_in, const int* in_sizes, int n_in,
                              void* d_out, int out_size)
{
    const float* x   = (const float*)d_in[0];
    const float* We0 = (const float*)d_in[1];
    const float* be0 = (const float*)d_in[2];
    const float* We1 = (const float*)d_in[3];
    const float* be1 = (const float*)d_in[4];
    const float* Wi  = (const float*)d_in[5];
    const float* bi  = (const float*)d_in[6];
    const float* Wd1 = (const float*)d_in[7];
    const float* bd1 = (const float*)d_in[8];
    const float* Wc1 = (const float*)d_in[9];
    const float* bc1 = (const float*)d_in[10];
    const float* Wd2 = (const float*)d_in[11];
    const float* bd2 = (const float*)d_in[12];
    const float* Wc2 = (const float*)d_in[13];
    const float* bc2_ = (const float*)d_in[14];
    const float* Wd3 = (const float*)d_in[15];
    const float* bd3 = (const float*)d_in[16];
    const float* Wc3 = (const float*)d_in[17];
    const float* bc3 = (const float*)d_in[18];
    const float* Wo  = (const float*)d_in[19];
    const float* bo  = (const float*)d_in[20];
    float* out = (float*)d_out;

    float *bufA, *bufB, *routed;
    cudaGetSymbolAddress((void**)&bufA, g_bufA);
    cudaGetSymbolAddress((void**)&bufB, g_bufB);
    cudaGetSymbolAddress((void**)&routed, g_routed);

    encoder_kernel<<<160, 256>>>(x, We0, be0, We1, be1);
    entropy_kernel<<<2048, 256>>>(x);
    median_kernel<<<1, 1024>>>();
    int write_aux = (out_size >= OUT_FULL) ? 1 : 0;
    route_kernel<<<128, 256>>>(out, write_aux);

    conv_launch(routed, Wi, bi, bufA, 4, 256, 32, 32, /*relu=*/0);     // h0  [8,256,32,32]
    deconv_launch(bufA, Wd1, bd1, bufB, 256, 256, 32, 32);             // t1  [8,256,64,64]
    conv_launch(bufB, Wc1, bc1, bufA, 256, 256, 64, 64, 1);            // h1
    deconv_launch(bufA, Wd2, bd2, bufB, 256, 128, 64, 64);             // t2  [8,128,128,128]
    conv_launch(bufB, Wc2, bc2_, bufA, 128, 128, 128, 128, 1);         // h2
    deconv_launch(bufA, Wd3, bd3, bufB, 128, 128, 128, 128);           // t3  [8,128,256,256]
    conv_launch(bufB, Wc3, bc3, bufA, 128, 128, 256, 256, 1);          // h3
    convWo_kernel<<<256, 256>>>(bufA, Wo, bo, out);                    // rec
}